// round 15
// baseline (speedup 1.0000x reference)
#include <cuda_runtime.h>
#include <cuda_bf16.h>
#include <math.h>

#define B_ 4
#define N_ 2048
#define C_ 384
#define K_ 10
#define ROWS_ (B_*N_)      // 8192
#define EDGES_ (ROWS_*K_)  // 81920
#define LDQ 1536
#define CAP_ 224

// ---------------- scratch ----------------
__device__ float g_Q[ROWS_*LDQ];
__device__ float g_Wbig[C_*LDQ];            // fp32 [k][n]
__device__ float g_bcat[LDQ];
__device__ __nv_bfloat16 g_qhi[ROWS_*C_];   // q split, [M,K]
__device__ __nv_bfloat16 g_qlo[ROWS_*C_];
__device__ __nv_bfloat16 g_wbhi[C_*LDQ];    // Wbig split, [K,N]
__device__ __nv_bfloat16 g_wblo[C_*LDQ];
__device__ int   g_knn[ROWS_*K_];
__device__ float g_scale[ROWS_*3];
__device__ int   g_i3[EDGES_*3];
__device__ float g_w3[EDGES_*3];

#define F_DST_WBIG 2

// ---------------- weight prep ----------------
__global__ void prep_wbig(const float* __restrict__ W1, const float* __restrict__ Wk) {
    int i = blockIdx.x * 256 + threadIdx.x;
    if (i >= C_ * (LDQ - C_)) return;
    int r = i / (LDQ - C_), c = i % (LDQ - C_);
    float v;
    if (c < C_)            v = W1[(C_ + r) * C_ + c];
    else if (c < 2 * C_)   v = Wk[r * C_ + (c - C_)];
    else                   v = Wk[(C_ + r) * C_ + (c - 2*C_)] - Wk[r * C_ + (c - 2*C_)];
    g_Wbig[r * LDQ + C_ + c] = v;
}

__global__ __launch_bounds__(256) void prep_bias(
    const float* __restrict__ bv, const float* __restrict__ W1,
    const float* __restrict__ b1, const float* __restrict__ bk)
{
    if (blockIdx.x < 48) {
        int w = threadIdx.x >> 5, lane = threadIdx.x & 31;
        int o = blockIdx.x * 8 + w;
        float s = 0.f;
        for (int t = 0; t < 12; t++) {
            int j = t * 32 + lane;
            s = fmaf(bv[j], W1[j * C_ + o], s);
        }
#pragma unroll
        for (int off = 16; off; off >>= 1) s += __shfl_xor_sync(0xffffffffu, s, off);
        if (lane == 0) g_bcat[o] = s;
    } else {
        int i = (blockIdx.x - 48) * 256 + threadIdx.x;
        if (i >= LDQ - C_) return;
        float v;
        if (i < C_)            v = b1[i];
        else if (i < 2 * C_)   v = 0.f;
        else                   v = bk[i - 2 * C_];
        g_bcat[C_ + i] = v;
    }
}

// ---------------- split conversions ----------------
__global__ void conv_q(const float* __restrict__ q) {
    int i = blockIdx.x * 256 + threadIdx.x;
    float x = q[i];
    __nv_bfloat16 h = __float2bfloat16(x);
    g_qhi[i] = h;
    g_qlo[i] = __float2bfloat16(x - __bfloat162float(h));
}

__global__ void conv_w() {
    int i = blockIdx.x * 256 + threadIdx.x;
    float x = g_Wbig[i];
    __nv_bfloat16 h = __float2bfloat16(x);
    g_wbhi[i] = h;
    g_wblo[i] = __float2bfloat16(x - __bfloat162float(h));
}

// ---------------- small fp32 SGEMM (W_A = Wv @ W1_top) ----------------
__global__ __launch_bounds__(256) void sgemm128(
    const float* __restrict__ Aex, const float* __restrict__ Bex,
    int flags, int M, int N, int K, int ldA, int ldB, int ldC)
{
    const float* A  = Aex;
    const float* Bm = Bex;
    float* Cm       = (flags & F_DST_WBIG) ? g_Wbig : g_Q;

    __shared__ float As[2][8][132];
    __shared__ float Bs[2][8][128];

    const int tid = threadIdx.x;
    const int tx = tid & 15;
    const int ty = tid >> 4;
    const int rowBase = blockIdx.y * 128;
    const int colBase = blockIdx.x * 128;

    const int arow = tid >> 1, acol = (tid & 1) * 4;
    const int brow = tid >> 5, bcol = (tid & 31) * 4;

    const float* Aptr = A + (size_t)(rowBase + arow) * ldA + acol;
    const float* Bptr = Bm + (size_t)brow * ldB + colBase + bcol;

    float4 aReg = *(const float4*)Aptr;
    float4 bReg = *(const float4*)Bptr;

    float acc[8][8];
#pragma unroll
    for (int i = 0; i < 8; i++)
#pragma unroll
        for (int j = 0; j < 8; j++) acc[i][j] = 0.f;

    As[0][acol + 0][arow] = aReg.x; As[0][acol + 1][arow] = aReg.y;
    As[0][acol + 2][arow] = aReg.z; As[0][acol + 3][arow] = aReg.w;
    *(float4*)&Bs[0][brow][bcol] = bReg;
    __syncthreads();

    const int nIter = K >> 3;
    int buf = 0;
    for (int it = 0; it < nIter; it++) {
        if (it + 1 < nIter) {
            aReg = *(const float4*)(Aptr + (it + 1) * 8);
            bReg = *(const float4*)(Bptr + (size_t)(it + 1) * 8 * ldB);
        }
#pragma unroll
        for (int kk = 0; kk < 8; kk++) {
            float4 a0 = *(const float4*)&As[buf][kk][ty * 4];
            float4 a1 = *(const float4*)&As[buf][kk][64 + ty * 4];
            float4 b0 = *(const float4*)&Bs[buf][kk][tx * 4];
            float4 b1 = *(const float4*)&Bs[buf][kk][64 + tx * 4];
            float am[8] = {a0.x, a0.y, a0.z, a0.w, a1.x, a1.y, a1.z, a1.w};
            float bn[8] = {b0.x, b0.y, b0.z, b0.w, b1.x, b1.y, b1.z, b1.w};
#pragma unroll
            for (int i = 0; i < 8; i++)
#pragma unroll
                for (int j = 0; j < 8; j++)
                    acc[i][j] = fmaf(am[i], bn[j], acc[i][j]);
        }
        if (it + 1 < nIter) {
            int nb = buf ^ 1;
            As[nb][acol + 0][arow] = aReg.x; As[nb][acol + 1][arow] = aReg.y;
            As[nb][acol + 2][arow] = aReg.z; As[nb][acol + 3][arow] = aReg.w;
            *(float4*)&Bs[nb][brow][bcol] = bReg;
            __syncthreads();
            buf = nb;
        }
    }
#pragma unroll
    for (int i = 0; i < 8; i++) {
        int r = rowBase + ((i < 4) ? (ty * 4 + i) : (64 + ty * 4 + i - 4));
        float* crow = Cm + (size_t)r * ldC + colBase;
        *(float4*)(crow + tx * 4) =
            make_float4(acc[i][0], acc[i][1], acc[i][2], acc[i][3]);
        *(float4*)(crow + 64 + tx * 4) =
            make_float4(acc[i][4], acc[i][5], acc[i][6], acc[i][7]);
    }
}

// ================= mma.sync split-bf16 GEMM, cp.async double-buffered =============
#define GA_HI 0
#define GA_LO 18432
#define GB_HI 36864
#define GB_LO 46080
#define G_STG 55296
#define G_TOT (2*G_STG)     // 110592

__device__ __forceinline__ unsigned smem_u32(const void* p) {
    unsigned a;
    asm("{ .reg .u64 t; cvta.to.shared.u64 t, %1; cvt.u32.u64 %0, t; }" : "=r"(a) : "l"(p));
    return a;
}
#define CP16(dst, src) \
    asm volatile("cp.async.cg.shared.global [%0], [%1], 16;" :: "r"(dst), "l"(src))
#define CP_COMMIT() asm volatile("cp.async.commit_group;" ::: "memory")
#define CP_WAIT0()  asm volatile("cp.async.wait_group 0;" ::: "memory")
#define CP_WAIT1()  asm volatile("cp.async.wait_group 1;" ::: "memory")
#define LDSM4(rg, addr) \
    asm volatile("ldmatrix.sync.aligned.m8n8.x4.shared.b16 {%0,%1,%2,%3}, [%4];" \
        : "=r"((rg)[0]), "=r"((rg)[1]), "=r"((rg)[2]), "=r"((rg)[3]) : "r"(addr))
#define LDSM4T(rg, addr) \
    asm volatile("ldmatrix.sync.aligned.m8n8.x4.trans.shared.b16 {%0,%1,%2,%3}, [%4];" \
        : "=r"((rg)[0]), "=r"((rg)[1]), "=r"((rg)[2]), "=r"((rg)[3]) : "r"(addr))
#define MMA16816(d, a, b0, b1) \
    asm volatile("mma.sync.aligned.m16n8k16.row.col.f32.bf16.bf16.f32 " \
        "{%0,%1,%2,%3}, {%4,%5,%6,%7}, {%8,%9}, {%0,%1,%2,%3};" \
        : "+f"((d)[0]), "+f"((d)[1]), "+f"((d)[2]), "+f"((d)[3]) \
        : "r"((a)[0]), "r"((a)[1]), "r"((a)[2]), "r"((a)[3]), "r"(b0), "r"(b1))

__device__ __forceinline__ void gemm_load_stage(
    unsigned base, int kc, int rowBase, int colBase, int tid)
{
#pragma unroll
    for (int t = 0; t < 4; t++) {
        int i = tid + t * 256;
        int r = i >> 3, c = i & 7;
        unsigned off = r * 144 + c * 16;
        size_t g = (size_t)(rowBase + r) * C_ + kc * 64 + c * 8;
        CP16(base + GA_HI + off, (const void*)(g_qhi + g));
        CP16(base + GA_LO + off, (const void*)(g_qlo + g));
    }
#pragma unroll
    for (int t = 0; t < 2; t++) {
        int i = tid + t * 256;
        int r = i >> 3, c = i & 7;
        unsigned off = r * 144 + c * 16;
        size_t g = (size_t)(kc * 64 + r) * LDQ + colBase + c * 8;
        CP16(base + GB_HI + off, (const void*)(g_wbhi + g));
        CP16(base + GB_LO + off, (const void*)(g_wblo + g));
    }
}

__global__ __launch_bounds__(256) void gemm_mma() {
    extern __shared__ char sm[];
    const unsigned sb = smem_u32(sm);
    const int tid = threadIdx.x;
    const int w = tid >> 5, lane = tid & 31;
    const int rowBase = blockIdx.y * 128;
    const int colBase = blockIdx.x * 64;
    const int wm = (w & 3) * 32;
    const int wn = (w >> 2) * 32;

    float acc[2][4][4];
#pragma unroll
    for (int mt = 0; mt < 2; mt++)
#pragma unroll
        for (int nt = 0; nt < 4; nt++)
#pragma unroll
            for (int j = 0; j < 4; j++) acc[mt][nt][j] = 0.f;

    const unsigned aRow = (lane & 15);
    const unsigned aKb  = (lane >> 4) << 4;
    const unsigned bK   = (lane & 7) + ((lane >> 3) & 1) * 8;
    const unsigned bN   = ((lane >> 4) & 1) * 8;

    gemm_load_stage(sb, 0, rowBase, colBase, tid);
    CP_COMMIT();

    for (int kc = 0; kc < 6; kc++) {
        const unsigned buf = sb + (kc & 1) * G_STG;
        if (kc + 1 < 6) {
            gemm_load_stage(sb + ((kc + 1) & 1) * G_STG, kc + 1, rowBase, colBase, tid);
            CP_COMMIT();
            CP_WAIT1();
        } else {
            CP_WAIT0();
        }
        __syncthreads();

#pragma unroll
        for (int ks = 0; ks < 4; ks++) {
            unsigned ahi[2][4], alo[2][4], bhi[2][4], blo[2][4];
#pragma unroll
            for (int mt = 0; mt < 2; mt++) {
                unsigned addr = buf + GA_HI + (wm + mt * 16 + aRow) * 144 + ks * 32 + aKb;
                LDSM4(ahi[mt], addr);
                LDSM4(alo[mt], addr + (GA_LO - GA_HI));
            }
#pragma unroll
            for (int ng = 0; ng < 2; ng++) {
                unsigned addr = buf + GB_HI + (ks * 16 + bK) * 144 + (wn + ng * 16 + bN) * 2;
                LDSM4T(bhi[ng], addr);
                LDSM4T(blo[ng], addr + (GB_LO - GB_HI));
            }
#pragma unroll
            for (int mt = 0; mt < 2; mt++)
#pragma unroll
                for (int nt = 0; nt < 4; nt++) {
                    unsigned bh0 = bhi[nt >> 1][(nt & 1) * 2];
                    unsigned bh1 = bhi[nt >> 1][(nt & 1) * 2 + 1];
                    unsigned bl0 = blo[nt >> 1][(nt & 1) * 2];
                    unsigned bl1 = blo[nt >> 1][(nt & 1) * 2 + 1];
                    MMA16816(acc[mt][nt], ahi[mt], bh0, bh1);
                    MMA16816(acc[mt][nt], ahi[mt], bl0, bl1);
                    MMA16816(acc[mt][nt], alo[mt], bh0, bh1);
                }
        }
        __syncthreads();
    }

#pragma unroll
    for (int mt = 0; mt < 2; mt++) {
        int m0 = rowBase + wm + mt * 16 + (lane >> 2);
#pragma unroll
        for (int nt = 0; nt < 4; nt++) {
            int c = colBase + wn + nt * 8 + 2 * (lane & 3);
            float bb0 = g_bcat[c], bb1 = g_bcat[c + 1];
            float* p0 = g_Q + (size_t)m0 * LDQ + c;
            float* p1 = g_Q + (size_t)(m0 + 8) * LDQ + c;
            p0[0] = acc[mt][nt][0] + bb0; p0[1] = acc[mt][nt][1] + bb1;
            p1[0] = acc[mt][nt][2] + bb0; p1[1] = acc[mt][nt][3] + bb1;
        }
    }
}

// ---------------- comparator ----------------
__device__ __forceinline__ bool dless(float d1, int i1, float d2, int i2) {
    return (d1 < d2) || (d1 == d2 && i1 < i2);
}
__device__ __forceinline__ float warp_sort32(float m, int lane) {
#pragma unroll
    for (int k = 2; k <= 32; k <<= 1) {
#pragma unroll
        for (int j = k >> 1; j > 0; j >>= 1) {
            float other = __shfl_xor_sync(0xffffffffu, m, j);
            bool up = ((lane & k) == 0);
            bool lower = ((lane & j) == 0);
            float mn = fminf(m, other), mx = fmaxf(m, other);
            m = (lower == up) ? mn : mx;
        }
    }
    return m;
}

// ---------------- kNN ----------------
__global__ __launch_bounds__(256) void knn_kernel(const float* __restrict__ q_pos) {
    __shared__ float4 sP[N_];
    __shared__ float  sBd[8][CAP_];
    __shared__ int    sBi[8][CAP_];
    const int qbase = blockIdx.x * 8;
    const int b = qbase >> 11;
    const float* P = q_pos + (size_t)b * N_ * 3;
    for (int i = threadIdx.x; i < N_; i += 256) {
        float x = P[i * 3 + 0], y = P[i * 3 + 1], z = P[i * 3 + 2];
        sP[i] = make_float4(x, y, z, x * x + y * y + z * z);
    }
    __syncthreads();
    const int w = threadIdx.x >> 5, lane = threadIdx.x & 31;
    const float FINF = __int_as_float(0x7f800000);

    const int qi = qbase + w;
    const float4 Q = sP[qi & (N_ - 1)];

    float m = FINF;
    for (int t = 0; t < N_ / 32; t++) {
        float4 c = sP[t * 32 + lane];
        float dot = Q.x * c.x + Q.y * c.y + Q.z * c.z;
        float dd = fmaf(dot, -2.f, c.w + Q.w);
        m = fminf(m, dd);
    }
    float s = warp_sort32(m, lane);
    float T    = __shfl_sync(0xffffffffu, s, K_ - 1);
    float Tmax = __shfl_sync(0xffffffffu, s, 31);

    int cnt = 0;
    float Tuse = T;
    for (int attempt = 0; attempt < 2; attempt++) {
        cnt = 0;
        for (int t = 0; t < N_ / 32; t++) {
            int cand = t * 32 + lane;
            float4 c = sP[cand];
            float dot = Q.x * c.x + Q.y * c.y + Q.z * c.z;
            float dd = fmaf(dot, -2.f, c.w + Q.w);
            bool p = (dd <= Tuse);
            unsigned mask = __ballot_sync(0xffffffffu, p);
            if (p) {
                int pos = cnt + __popc(mask & ((1u << lane) - 1u));
                if (pos < CAP_) { sBd[w][pos] = dd; sBi[w][pos] = cand; }
            }
            cnt += __popc(mask);
        }
        if (cnt >= K_) break;
        Tuse = Tmax;
    }
    int n = cnt < CAP_ ? cnt : CAP_;
    __syncwarp();

    float mnx = FINF, mny = FINF, mnz = FINF;
    float mxx = -FINF, mxy = -FINF, mxz = -FINF;
    for (int r = 0; r < K_; r++) {
        float bd = FINF; int bi = 0x7fffffff;
        for (int i = lane; i < n; i += 32) {
            float dd = sBd[w][i]; int ii = sBi[w][i];
            if (dless(dd, ii, bd, bi)) { bd = dd; bi = ii; }
        }
#pragma unroll
        for (int off = 16; off; off >>= 1) {
            float od = __shfl_xor_sync(0xffffffffu, bd, off);
            int   oi = __shfl_xor_sync(0xffffffffu, bi, off);
            if (dless(od, oi, bd, bi)) { bd = od; bi = oi; }
        }
        if (lane == 0) g_knn[qi * K_ + r] = bi;
        float4 wp = sP[bi];
        mnx = fminf(mnx, wp.x); mxx = fmaxf(mxx, wp.x);
        mny = fminf(mny, wp.y); mxy = fmaxf(mxy, wp.y);
        mnz = fminf(mnz, wp.z); mxz = fmaxf(mxz, wp.z);
        for (int i = lane; i < n; i += 32)
            if (sBi[w][i] == bi) sBd[w][i] = FINF;
        __syncwarp();
    }
    if (lane == 0) {
        g_scale[qi * 3 + 0] = (mxx - mnx) * 0.5f;
        g_scale[qi * 3 + 1] = (mxy - mny) * 0.5f;
        g_scale[qi * 3 + 2] = (mxz - mnz) * 0.5f;
    }
}

// ======= fused edge kernel: per-edge MLP -> shift -> exact three-NN =======
// Block = 8 warps = 8 points = 80 edges. sP staged once, shifts via smem.
__global__ __launch_bounds__(256) void edge_kernel(
    const float* __restrict__ q_pos, const float* __restrict__ ln_g,
    const float* __restrict__ ln_b, const float* __restrict__ W2)
{
    __shared__ float4 sP[N_];
    __shared__ float  sSh[8][K_][3];
    const int pbase = blockIdx.x * 8;
    const int b = pbase >> 11;
    const float* P = q_pos + (size_t)b * N_ * 3;
    for (int i = threadIdx.x; i < N_; i += 256) {
        float x = P[i * 3 + 0], y = P[i * 3 + 1], z = P[i * 3 + 2];
        sP[i] = make_float4(x, y, z, x * x + y * y + z * z);
    }
    __syncthreads();

    const int w = threadIdx.x >> 5, lane = threadIdx.x & 31;
    const int p = pbase + w;
    const int c0 = lane * 12;
    const float FINF = __int_as_float(0x7f800000);

    // ---- phase 1: MLP + shifts (identical math to prior offset_kernel) ----
    {
        float4 bq[3], lg[3], lb[3], w2f[9];
        const float* Bq = g_Q + (size_t)p * LDQ + C_ + c0;
#pragma unroll
        for (int t = 0; t < 3; t++) {
            bq[t] = *(const float4*)(Bq + t * 4);
            lg[t] = *(const float4*)(ln_g + c0 + t * 4);
            lb[t] = *(const float4*)(ln_b + c0 + t * 4);
        }
#pragma unroll
        for (int t = 0; t < 9; t++) w2f[t] = *(const float4*)(W2 + c0 * 3 + t * 4);
        const float* w2s = (const float*)w2f;
        const float* bqs = (const float*)bq;
        const float* lgs = (const float*)lg;
        const float* lbs = (const float*)lb;

        const float sx = g_scale[p * 3 + 0];
        const float sy = g_scale[p * 3 + 1];
        const float sz = g_scale[p * 3 + 2];

        for (int k = 0; k < K_; k++) {
            const int nb = g_knn[p * K_ + k];
            const float* Arow = g_Q + (size_t)(b * N_ + nb) * LDQ + c0;

            float h[12];
            float4 a0 = *(const float4*)(Arow);
            float4 a1 = *(const float4*)(Arow + 4);
            float4 a2 = *(const float4*)(Arow + 8);
            h[0] = a0.x + bqs[0]; h[1] = a0.y + bqs[1]; h[2] = a0.z + bqs[2]; h[3] = a0.w + bqs[3];
            h[4] = a1.x + bqs[4]; h[5] = a1.y + bqs[5]; h[6] = a1.z + bqs[6]; h[7] = a1.w + bqs[7];
            h[8] = a2.x + bqs[8]; h[9] = a2.y + bqs[9]; h[10]= a2.z + bqs[10];h[11]= a2.w + bqs[11];

            float s = 0.f;
#pragma unroll
            for (int j = 0; j < 12; j++) s += h[j];
#pragma unroll
            for (int off = 16; off; off >>= 1) s += __shfl_xor_sync(0xffffffffu, s, off);
            float mu = s * (1.f / C_);
            float v = 0.f;
#pragma unroll
            for (int j = 0; j < 12; j++) { float t = h[j] - mu; v += t * t; }
#pragma unroll
            for (int off = 16; off; off >>= 1) v += __shfl_xor_sync(0xffffffffu, v, off);
            float rstd = rsqrtf(v * (1.f / C_) + 1e-5f);

            float s0 = 0.f, s1 = 0.f, s2 = 0.f;
#pragma unroll
            for (int j = 0; j < 12; j++) {
                float g = (h[j] - mu) * rstd * lgs[j] + lbs[j];
                float y = 0.5f * g * (1.f + erff(g * 0.70710678118654752f));
                s0 = fmaf(y, w2s[j * 3 + 0], s0);
                s1 = fmaf(y, w2s[j * 3 + 1], s1);
                s2 = fmaf(y, w2s[j * 3 + 2], s2);
            }
#pragma unroll
            for (int off = 16; off; off >>= 1) {
                s0 += __shfl_xor_sync(0xffffffffu, s0, off);
                s1 += __shfl_xor_sync(0xffffffffu, s1, off);
                s2 += __shfl_xor_sync(0xffffffffu, s2, off);
            }
            if (lane == 0) {
                float4 pp = sP[nb];
                sSh[w][k][0] = fmaf(tanhf(s0), sx, pp.x);
                sSh[w][k][1] = fmaf(tanhf(s1), sy, pp.y);
                sSh[w][k][2] = fmaf(tanhf(s2), sz, pp.z);
            }
        }
    }
    __syncwarp();

    // ---- phase 2: three-NN, 5 edges per scan pass ----
#pragma unroll
    for (int g = 0; g < 2; g++) {
        float px[5], py[5], pz[5], qw[5];
#pragma unroll
        for (int j = 0; j < 5; j++) {
            px[j] = sSh[w][g * 5 + j][0];
            py[j] = sSh[w][g * 5 + j][1];
            pz[j] = sSh[w][g * 5 + j][2];
            qw[j] = px[j] * px[j] + py[j] * py[j] + pz[j] * pz[j];
        }
        float d0[5], d1[5], d2[5];
        int   i0[5], i1[5], i2[5];
#pragma unroll
        for (int j = 0; j < 5; j++) {
            d0[j] = d1[j] = d2[j] = FINF;
            i0[j] = i1[j] = i2[j] = 0x7fffffff;
        }

        for (int t = 0; t < N_ / 32; t++) {
            int cand = t * 32 + lane;
            float4 c = sP[cand];
#pragma unroll
            for (int j = 0; j < 5; j++) {
                float dot = px[j] * c.x + py[j] * c.y + pz[j] * c.z;
                float dp = fmaf(dot, -2.f, c.w);
                if (dp < d2[j]) {
                    if (dp < d1[j]) {
                        d2[j] = d1[j]; i2[j] = i1[j];
                        if (dp < d0[j]) {
                            d1[j] = d0[j]; i1[j] = i0[j];
                            d0[j] = dp;    i0[j] = cand;
                        } else {
                            d1[j] = dp;    i1[j] = cand;
                        }
                    } else {
                        d2[j] = dp; i2[j] = cand;
                    }
                }
            }
        }

#pragma unroll
        for (int j = 0; j < 5; j++) {
            float rd[3]; int ri[3];
            float a0 = d0[j], a1 = d1[j], a2 = d2[j];
            int   b0 = i0[j], b1 = i1[j], b2 = i2[j];
#pragma unroll
            for (int r = 0; r < 3; r++) {
                float bd = a0; int bi = b0;
#pragma unroll
                for (int off = 16; off; off >>= 1) {
                    float od = __shfl_xor_sync(0xffffffffu, bd, off);
                    int   oi = __shfl_xor_sync(0xffffffffu, bi, off);
                    if (dless(od, oi, bd, bi)) { bd = od; bi = oi; }
                }
                rd[r] = bd; ri[r] = bi;
                if (b0 == bi) { a0 = a1; b0 = b1; a1 = a2; b1 = b2;
                                a2 = FINF; b2 = 0x7fffffff; }
            }
            if (lane == 0) {
                const int e = p * K_ + g * 5 + j;
                float r0 = 1.f / (rd[0] + qw[j] + 1e-8f);
                float r1 = 1.f / (rd[1] + qw[j] + 1e-8f);
                float r2 = 1.f / (rd[2] + qw[j] + 1e-8f);
                float sm = r0 + r1 + r2;
                g_i3[e * 3 + 0] = ri[0]; g_w3[e * 3 + 0] = r0 / sm;
                g_i3[e * 3 + 1] = ri[1]; g_w3[e * 3 + 1] = r1 / sm;
                g_i3[e * 3 + 2] = ri[2]; g_w3[e * 3 + 2] = r2 / sm;
            }
        }
    }
}

// ---------------- final ----------------
__global__ __launch_bounds__(96) void final_kernel(float* __restrict__ out) {
    const int row = blockIdx.x;
    const int b = row >> 11;
    const int tid = threadIdx.x;
    __shared__ int   sI[K_ * 3];
    __shared__ float sW[K_ * 3];
    const int e0 = row * K_;
    if (tid < K_ * 3) { sI[tid] = g_i3[e0 * 3 + tid]; sW[tid] = g_w3[e0 * 3 + tid]; }
    __syncthreads();

    const size_t baseB = (size_t)b * N_ * LDQ;
    float4 qp = *(const float4*)(g_Q + (size_t)row * LDQ + 3 * C_ + tid * 4);
    const float NINF = __int_as_float(0xff800000);
    float4 mx = make_float4(NINF, NINF, NINF, NINF);

    for (int k = 0; k < K_; k++) {
        int   a0 = sI[3 * k + 0], a1 = sI[3 * k + 1], a2 = sI[3 * k + 2];
        float w0 = sW[3 * k + 0], w1 = sW[3 * k + 1], w2 = sW[3 * k + 2];
        float4 r0 = *(const float4*)(g_Q + baseB + (size_t)a0 * LDQ + 2 * C_ + tid * 4);
        float4 r1 = *(const float4*)(g_Q + baseB + (size_t)a1 * LDQ + 2 * C_ + tid * 4);
        float4 r2 = *(const float4*)(g_Q + baseB + (size_t)a2 * LDQ + 2 * C_ + tid * 4);
        float v0 = qp.x + w0 * r0.x + w1 * r1.x + w2 * r2.x;
        float v1 = qp.y + w0 * r0.y + w1 * r1.y + w2 * r2.y;
        float v2 = qp.z + w0 * r0.z + w1 * r1.z + w2 * r2.z;
        float v3 = qp.w + w0 * r0.w + w1 * r1.w + w2 * r2.w;
        v0 = v0 > 0.f ? v0 : 0.2f * v0;
        v1 = v1 > 0.f ? v1 : 0.2f * v1;
        v2 = v2 > 0.f ? v2 : 0.2f * v2;
        v3 = v3 > 0.f ? v3 : 0.2f * v3;
        mx.x = fmaxf(mx.x, v0); mx.y = fmaxf(mx.y, v1);
        mx.z = fmaxf(mx.z, v2); mx.w = fmaxf(mx.w, v3);
    }
    *(float4*)(out + (size_t)row * C_ + tid * 4) = mx;
}

// ---------------- launch ----------------
extern "C" void kernel_launch(void* const* d_in, const int* in_sizes, int n_in,
                              void* d_out, int out_size) {
    const float* q     = (const float*)d_in[0];
    const float* q_pos = (const float*)d_in[1];
    const float* Wv    = (const float*)d_in[2];
    const float* bv    = (const float*)d_in[3];
    const float* W1    = (const float*)d_in[4];
    const float* b1    = (const float*)d_in[5];
    const float* ln_g  = (const float*)d_in[6];
    const float* ln_b  = (const float*)d_in[7];
    const float* W2    = (const float*)d_in[8];
    const float* Wk    = (const float*)d_in[9];
    const float* bk    = (const float*)d_in[10];

    cudaFuncSetAttribute(gemm_mma, cudaFuncAttributeMaxDynamicSharedMemorySize, G_TOT);

    prep_wbig<<<(C_ * (LDQ - C_) + 255) / 256, 256>>>(W1, Wk);
    prep_bias<<<48 + (LDQ - C_ + 255) / 256, 256>>>(bv, W1, b1, bk);
    sgemm128<<<dim3(C_ / 128, C_ / 128), 256>>>(Wv, W1, F_DST_WBIG,
                                                C_, C_, C_, C_, C_, LDQ);
    conv_w<<<(C_ * LDQ) / 256, 256>>>();
    conv_q<<<(ROWS_ * C_) / 256, 256>>>(q);
    knn_kernel<<<ROWS_ / 8, 256>>>(q_pos);
    gemm_mma<<<dim3(LDQ / 64, ROWS_ / 128), 256, G_TOT>>>();
    edge_kernel<<<ROWS_ / 8, 256>>>(q_pos, ln_g, ln_b, W2);
    final_kernel<<<ROWS_, 96>>>((float*)d_out);
}

// round 17
// speedup vs baseline: 1.0450x; 1.0450x over previous
#include <cuda_runtime.h>
#include <cuda_bf16.h>
#include <math.h>

#define B_ 4
#define N_ 2048
#define C_ 384
#define K_ 10
#define ROWS_ (B_*N_)      // 8192
#define EDGES_ (ROWS_*K_)  // 81920
#define LDQ 1536
#define CAP_ 224

// ---------------- scratch ----------------
__device__ float g_Q[ROWS_*LDQ];
__device__ float g_Wbig[C_*LDQ];            // fp32 [k][n]
__device__ float g_bcat[LDQ];
__device__ __nv_bfloat16 g_qhi[ROWS_*C_];
__device__ __nv_bfloat16 g_qlo[ROWS_*C_];
__device__ __nv_bfloat16 g_wbhi[C_*LDQ];    // [K,N]
__device__ __nv_bfloat16 g_wblo[C_*LDQ];
__device__ int   g_knn[ROWS_*K_];
__device__ float g_scale[ROWS_*3];
__device__ float g_shift[EDGES_*3];
__device__ int   g_i3[EDGES_*3];
__device__ float g_w3[EDGES_*3];

#define F_DST_WBIG 2

// ---------------- weight prep ----------------
__global__ void prep_wbig(const float* __restrict__ W1, const float* __restrict__ Wk) {
    int i = blockIdx.x * 256 + threadIdx.x;
    if (i >= C_ * (LDQ - C_)) return;
    int r = i / (LDQ - C_), c = i % (LDQ - C_);
    float v;
    if (c < C_)            v = W1[(C_ + r) * C_ + c];
    else if (c < 2 * C_)   v = Wk[r * C_ + (c - C_)];
    else                   v = Wk[(C_ + r) * C_ + (c - 2*C_)] - Wk[r * C_ + (c - 2*C_)];
    g_Wbig[r * LDQ + C_ + c] = v;
}

__global__ __launch_bounds__(256) void prep_bias(
    const float* __restrict__ bv, const float* __restrict__ W1,
    const float* __restrict__ b1, const float* __restrict__ bk)
{
    if (blockIdx.x < 48) {
        int w = threadIdx.x >> 5, lane = threadIdx.x & 31;
        int o = blockIdx.x * 8 + w;
        float s = 0.f;
        for (int t = 0; t < 12; t++) {
            int j = t * 32 + lane;
            s = fmaf(bv[j], W1[j * C_ + o], s);
        }
#pragma unroll
        for (int off = 16; off; off >>= 1) s += __shfl_xor_sync(0xffffffffu, s, off);
        if (lane == 0) g_bcat[o] = s;
    } else {
        int i = (blockIdx.x - 48) * 256 + threadIdx.x;
        if (i >= LDQ - C_) return;
        float v;
        if (i < C_)            v = b1[i];
        else if (i < 2 * C_)   v = 0.f;
        else                   v = bk[i - 2 * C_];
        g_bcat[C_ + i] = v;
    }
}

// ---------------- merged split conversion: q then Wbig ----------------
#define QELEMS (ROWS_*C_)     // 3145728 -> 12288 blocks
#define WELEMS (C_*LDQ)       // 589824  -> 2304 blocks
__global__ void conv_all(const float* __restrict__ q) {
    int blk = blockIdx.x;
    if (blk < QELEMS / 256) {
        int i = blk * 256 + threadIdx.x;
        float x = q[i];
        __nv_bfloat16 h = __float2bfloat16(x);
        g_qhi[i] = h;
        g_qlo[i] = __float2bfloat16(x - __bfloat162float(h));
    } else {
        int i = (blk - QELEMS / 256) * 256 + threadIdx.x;
        float x = g_Wbig[i];
        __nv_bfloat16 h = __float2bfloat16(x);
        g_wbhi[i] = h;
        g_wblo[i] = __float2bfloat16(x - __bfloat162float(h));
    }
}

// ---------------- small fp32 SGEMM (W_A = Wv @ W1_top) ----------------
__global__ __launch_bounds__(256) void sgemm128(
    const float* __restrict__ Aex, const float* __restrict__ Bex,
    int flags, int M, int N, int K, int ldA, int ldB, int ldC)
{
    const float* A  = Aex;
    const float* Bm = Bex;
    float* Cm       = (flags & F_DST_WBIG) ? g_Wbig : g_Q;

    __shared__ float As[2][8][132];
    __shared__ float Bs[2][8][128];

    const int tid = threadIdx.x;
    const int tx = tid & 15;
    const int ty = tid >> 4;
    const int rowBase = blockIdx.y * 128;
    const int colBase = blockIdx.x * 128;

    const int arow = tid >> 1, acol = (tid & 1) * 4;
    const int brow = tid >> 5, bcol = (tid & 31) * 4;

    const float* Aptr = A + (size_t)(rowBase + arow) * ldA + acol;
    const float* Bptr = Bm + (size_t)brow * ldB + colBase + bcol;

    float4 aReg = *(const float4*)Aptr;
    float4 bReg = *(const float4*)Bptr;

    float acc[8][8];
#pragma unroll
    for (int i = 0; i < 8; i++)
#pragma unroll
        for (int j = 0; j < 8; j++) acc[i][j] = 0.f;

    As[0][acol + 0][arow] = aReg.x; As[0][acol + 1][arow] = aReg.y;
    As[0][acol + 2][arow] = aReg.z; As[0][acol + 3][arow] = aReg.w;
    *(float4*)&Bs[0][brow][bcol] = bReg;
    __syncthreads();

    const int nIter = K >> 3;
    int buf = 0;
    for (int it = 0; it < nIter; it++) {
        if (it + 1 < nIter) {
            aReg = *(const float4*)(Aptr + (it + 1) * 8);
            bReg = *(const float4*)(Bptr + (size_t)(it + 1) * 8 * ldB);
        }
#pragma unroll
        for (int kk = 0; kk < 8; kk++) {
            float4 a0 = *(const float4*)&As[buf][kk][ty * 4];
            float4 a1 = *(const float4*)&As[buf][kk][64 + ty * 4];
            float4 b0 = *(const float4*)&Bs[buf][kk][tx * 4];
            float4 b1 = *(const float4*)&Bs[buf][kk][64 + tx * 4];
            float am[8] = {a0.x, a0.y, a0.z, a0.w, a1.x, a1.y, a1.z, a1.w};
            float bn[8] = {b0.x, b0.y, b0.z, b0.w, b1.x, b1.y, b1.z, b1.w};
#pragma unroll
            for (int i = 0; i < 8; i++)
#pragma unroll
                for (int j = 0; j < 8; j++)
                    acc[i][j] = fmaf(am[i], bn[j], acc[i][j]);
        }
        if (it + 1 < nIter) {
            int nb = buf ^ 1;
            As[nb][acol + 0][arow] = aReg.x; As[nb][acol + 1][arow] = aReg.y;
            As[nb][acol + 2][arow] = aReg.z; As[nb][acol + 3][arow] = aReg.w;
            *(float4*)&Bs[nb][brow][bcol] = bReg;
            __syncthreads();
            buf = nb;
        }
    }
#pragma unroll
    for (int i = 0; i < 8; i++) {
        int r = rowBase + ((i < 4) ? (ty * 4 + i) : (64 + ty * 4 + i - 4));
        float* crow = Cm + (size_t)r * ldC + colBase;
        *(float4*)(crow + tx * 4) =
            make_float4(acc[i][0], acc[i][1], acc[i][2], acc[i][3]);
        *(float4*)(crow + 64 + tx * 4) =
            make_float4(acc[i][4], acc[i][5], acc[i][6], acc[i][7]);
    }
}

// ================= mma.sync split-bf16 GEMM, cp.async double-buffered =============
#define GA_HI 0
#define GA_LO 18432
#define GB_HI 36864
#define GB_LO 46080
#define G_STG 55296
#define G_TOT (2*G_STG)     // 110592

__device__ __forceinline__ unsigned smem_u32(const void* p) {
    unsigned a;
    asm("{ .reg .u64 t; cvta.to.shared.u64 t, %1; cvt.u32.u64 %0, t; }" : "=r"(a) : "l"(p));
    return a;
}
#define CP16(dst, src) \
    asm volatile("cp.async.cg.shared.global [%0], [%1], 16;" :: "r"(dst), "l"(src))
#define CP_COMMIT() asm volatile("cp.async.commit_group;" ::: "memory")
#define CP_WAIT0()  asm volatile("cp.async.wait_group 0;" ::: "memory")
#define CP_WAIT1()  asm volatile("cp.async.wait_group 1;" ::: "memory")
#define LDSM4(rg, addr) \
    asm volatile("ldmatrix.sync.aligned.m8n8.x4.shared.b16 {%0,%1,%2,%3}, [%4];" \
        : "=r"((rg)[0]), "=r"((rg)[1]), "=r"((rg)[2]), "=r"((rg)[3]) : "r"(addr))
#define LDSM4T(rg, addr) \
    asm volatile("ldmatrix.sync.aligned.m8n8.x4.trans.shared.b16 {%0,%1,%2,%3}, [%4];" \
        : "=r"((rg)[0]), "=r"((rg)[1]), "=r"((rg)[2]), "=r"((rg)[3]) : "r"(addr))
#define MMA16816(d, a, b0, b1) \
    asm volatile("mma.sync.aligned.m16n8k16.row.col.f32.bf16.bf16.f32 " \
        "{%0,%1,%2,%3}, {%4,%5,%6,%7}, {%8,%9}, {%0,%1,%2,%3};" \
        : "+f"((d)[0]), "+f"((d)[1]), "+f"((d)[2]), "+f"((d)[3]) \
        : "r"((a)[0]), "r"((a)[1]), "r"((a)[2]), "r"((a)[3]), "r"(b0), "r"(b1))

__device__ __forceinline__ void gemm_load_stage(
    unsigned base, int kc, int rowBase, int colBase, int tid)
{
#pragma unroll
    for (int t = 0; t < 4; t++) {
        int i = tid + t * 256;
        int r = i >> 3, c = i & 7;
        unsigned off = r * 144 + c * 16;
        size_t g = (size_t)(rowBase + r) * C_ + kc * 64 + c * 8;
        CP16(base + GA_HI + off, (const void*)(g_qhi + g));
        CP16(base + GA_LO + off, (const void*)(g_qlo + g));
    }
#pragma unroll
    for (int t = 0; t < 2; t++) {
        int i = tid + t * 256;
        int r = i >> 3, c = i & 7;
        unsigned off = r * 144 + c * 16;
        size_t g = (size_t)(kc * 64 + r) * LDQ + colBase + c * 8;
        CP16(base + GB_HI + off, (const void*)(g_wbhi + g));
        CP16(base + GB_LO + off, (const void*)(g_wblo + g));
    }
}

__global__ __launch_bounds__(256) void gemm_mma() {
    extern __shared__ char sm[];
    const unsigned sb = smem_u32(sm);
    const int tid = threadIdx.x;
    const int w = tid >> 5, lane = tid & 31;
    const int rowBase = blockIdx.y * 128;
    const int colBase = blockIdx.x * 64;
    const int wm = (w & 3) * 32;
    const int wn = (w >> 2) * 32;

    float acc[2][4][4];
#pragma unroll
    for (int mt = 0; mt < 2; mt++)
#pragma unroll
        for (int nt = 0; nt < 4; nt++)
#pragma unroll
            for (int j = 0; j < 4; j++) acc[mt][nt][j] = 0.f;

    const unsigned aRow = (lane & 15);
    const unsigned aKb  = (lane >> 4) << 4;
    const unsigned bK   = (lane & 7) + ((lane >> 3) & 1) * 8;
    const unsigned bN   = ((lane >> 4) & 1) * 8;

    gemm_load_stage(sb, 0, rowBase, colBase, tid);
    CP_COMMIT();

    for (int kc = 0; kc < 6; kc++) {
        const unsigned buf = sb + (kc & 1) * G_STG;
        if (kc + 1 < 6) {
            gemm_load_stage(sb + ((kc + 1) & 1) * G_STG, kc + 1, rowBase, colBase, tid);
            CP_COMMIT();
            CP_WAIT1();
        } else {
            CP_WAIT0();
        }
        __syncthreads();

#pragma unroll
        for (int ks = 0; ks < 4; ks++) {
            unsigned ahi[2][4], alo[2][4], bhi[2][4], blo[2][4];
#pragma unroll
            for (int mt = 0; mt < 2; mt++) {
                unsigned addr = buf + GA_HI + (wm + mt * 16 + aRow) * 144 + ks * 32 + aKb;
                LDSM4(ahi[mt], addr);
                LDSM4(alo[mt], addr + (GA_LO - GA_HI));
            }
#pragma unroll
            for (int ng = 0; ng < 2; ng++) {
                unsigned addr = buf + GB_HI + (ks * 16 + bK) * 144 + (wn + ng * 16 + bN) * 2;
                LDSM4T(bhi[ng], addr);
                LDSM4T(blo[ng], addr + (GB_LO - GB_HI));
            }
#pragma unroll
            for (int mt = 0; mt < 2; mt++)
#pragma unroll
                for (int nt = 0; nt < 4; nt++) {
                    unsigned bh0 = bhi[nt >> 1][(nt & 1) * 2];
                    unsigned bh1 = bhi[nt >> 1][(nt & 1) * 2 + 1];
                    unsigned bl0 = blo[nt >> 1][(nt & 1) * 2];
                    unsigned bl1 = blo[nt >> 1][(nt & 1) * 2 + 1];
                    MMA16816(acc[mt][nt], ahi[mt], bh0, bh1);
                    MMA16816(acc[mt][nt], ahi[mt], bl0, bl1);
                    MMA16816(acc[mt][nt], alo[mt], bh0, bh1);
                }
        }
        __syncthreads();
    }

#pragma unroll
    for (int mt = 0; mt < 2; mt++) {
        int m0 = rowBase + wm + mt * 16 + (lane >> 2);
#pragma unroll
        for (int nt = 0; nt < 4; nt++) {
            int c = colBase + wn + nt * 8 + 2 * (lane & 3);
            float bb0 = g_bcat[c], bb1 = g_bcat[c + 1];
            float* p0 = g_Q + (size_t)m0 * LDQ + c;
            float* p1 = g_Q + (size_t)(m0 + 8) * LDQ + c;
            p0[0] = acc[mt][nt][0] + bb0; p0[1] = acc[mt][nt][1] + bb1;
            p1[0] = acc[mt][nt][2] + bb0; p1[1] = acc[mt][nt][3] + bb1;
        }
    }
}

// ---------------- comparator ----------------
__device__ __forceinline__ bool dless(float d1, int i1, float d2, int i2) {
    return (d1 < d2) || (d1 == d2 && i1 < i2);
}
__device__ __forceinline__ float warp_sort32(float m, int lane) {
#pragma unroll
    for (int k = 2; k <= 32; k <<= 1) {
#pragma unroll
        for (int j = k >> 1; j > 0; j >>= 1) {
            float other = __shfl_xor_sync(0xffffffffu, m, j);
            bool up = ((lane & k) == 0);
            bool lower = ((lane & j) == 0);
            float mn = fminf(m, other), mx = fmaxf(m, other);
            m = (lower == up) ? mn : mx;
        }
    }
    return m;
}

// ---------------- kNN ----------------
__global__ __launch_bounds__(256) void knn_kernel(const float* __restrict__ q_pos) {
    __shared__ float4 sP[N_];
    __shared__ float  sBd[8][CAP_];
    __shared__ int    sBi[8][CAP_];
    const int qbase = blockIdx.x * 8;
    const int b = qbase >> 11;
    const float* P = q_pos + (size_t)b * N_ * 3;
    for (int i = threadIdx.x; i < N_; i += 256) {
        float x = P[i * 3 + 0], y = P[i * 3 + 1], z = P[i * 3 + 2];
        sP[i] = make_float4(x, y, z, x * x + y * y + z * z);
    }
    __syncthreads();
    const int w = threadIdx.x >> 5, lane = threadIdx.x & 31;
    const float FINF = __int_as_float(0x7f800000);

    const int qi = qbase + w;
    const float4 Q = sP[qi & (N_ - 1)];

    float m = FINF;
    for (int t = 0; t < N_ / 32; t++) {
        float4 c = sP[t * 32 + lane];
        float dot = Q.x * c.x + Q.y * c.y + Q.z * c.z;
        float dd = fmaf(dot, -2.f, c.w + Q.w);
        m = fminf(m, dd);
    }
    float s = warp_sort32(m, lane);
    float T    = __shfl_sync(0xffffffffu, s, K_ - 1);
    float Tmax = __shfl_sync(0xffffffffu, s, 31);

    int cnt = 0;
    float Tuse = T;
    for (int attempt = 0; attempt < 2; attempt++) {
        cnt = 0;
        for (int t = 0; t < N_ / 32; t++) {
            int cand = t * 32 + lane;
            float4 c = sP[cand];
            float dot = Q.x * c.x + Q.y * c.y + Q.z * c.z;
            float dd = fmaf(dot, -2.f, c.w + Q.w);
            bool p = (dd <= Tuse);
            unsigned mask = __ballot_sync(0xffffffffu, p);
            if (p) {
                int pos = cnt + __popc(mask & ((1u << lane) - 1u));
                if (pos < CAP_) { sBd[w][pos] = dd; sBi[w][pos] = cand; }
            }
            cnt += __popc(mask);
        }
        if (cnt >= K_) break;
        Tuse = Tmax;
    }
    int n = cnt < CAP_ ? cnt : CAP_;
    __syncwarp();

    float mnx = FINF, mny = FINF, mnz = FINF;
    float mxx = -FINF, mxy = -FINF, mxz = -FINF;
    for (int r = 0; r < K_; r++) {
        float bd = FINF; int bi = 0x7fffffff;
        for (int i = lane; i < n; i += 32) {
            float dd = sBd[w][i]; int ii = sBi[w][i];
            if (dless(dd, ii, bd, bi)) { bd = dd; bi = ii; }
        }
#pragma unroll
        for (int off = 16; off; off >>= 1) {
            float od = __shfl_xor_sync(0xffffffffu, bd, off);
            int   oi = __shfl_xor_sync(0xffffffffu, bi, off);
            if (dless(od, oi, bd, bi)) { bd = od; bi = oi; }
        }
        if (lane == 0) g_knn[qi * K_ + r] = bi;
        float4 wp = sP[bi];
        mnx = fminf(mnx, wp.x); mxx = fmaxf(mxx, wp.x);
        mny = fminf(mny, wp.y); mxy = fmaxf(mxy, wp.y);
        mnz = fminf(mnz, wp.z); mxz = fmaxf(mxz, wp.z);
        for (int i = lane; i < n; i += 32)
            if (sBi[w][i] == bi) sBd[w][i] = FINF;
        __syncwarp();
    }
    if (lane == 0) {
        g_scale[qi * 3 + 0] = (mxx - mnx) * 0.5f;
        g_scale[qi * 3 + 1] = (mxy - mny) * 0.5f;
        g_scale[qi * 3 + 2] = (mxz - mnz) * 0.5f;
    }
}

// ---------------- per-point MLP (R12 version) ----------------
__global__ __launch_bounds__(256) void offset_kernel(
    const float* __restrict__ q_pos, const float* __restrict__ ln_g,
    const float* __restrict__ ln_b, const float* __restrict__ W2)
{
    const int w = threadIdx.x >> 5, lane = threadIdx.x & 31;
    const int p = blockIdx.x * 8 + w;
    const int b = p >> 11;
    const int c0 = lane * 12;

    float4 bq[3], lg[3], lb[3], w2f[9];
    const float* Bq = g_Q + (size_t)p * LDQ + C_ + c0;
#pragma unroll
    for (int t = 0; t < 3; t++) {
        bq[t] = *(const float4*)(Bq + t * 4);
        lg[t] = *(const float4*)(ln_g + c0 + t * 4);
        lb[t] = *(const float4*)(ln_b + c0 + t * 4);
    }
#pragma unroll
    for (int t = 0; t < 9; t++) w2f[t] = *(const float4*)(W2 + c0 * 3 + t * 4);
    const float* w2s = (const float*)w2f;
    const float* bqs = (const float*)bq;
    const float* lgs = (const float*)lg;
    const float* lbs = (const float*)lb;

    const float sx = g_scale[p * 3 + 0];
    const float sy = g_scale[p * 3 + 1];
    const float sz = g_scale[p * 3 + 2];

    for (int k = 0; k < K_; k++) {
        const int nb = g_knn[p * K_ + k];
        const int rownb = b * N_ + nb;
        const float* Arow = g_Q + (size_t)rownb * LDQ + c0;

        float h[12];
        float4 a0 = *(const float4*)(Arow);
        float4 a1 = *(const float4*)(Arow + 4);
        float4 a2 = *(const float4*)(Arow + 8);
        h[0] = a0.x + bqs[0]; h[1] = a0.y + bqs[1]; h[2] = a0.z + bqs[2]; h[3] = a0.w + bqs[3];
        h[4] = a1.x + bqs[4]; h[5] = a1.y + bqs[5]; h[6] = a1.z + bqs[6]; h[7] = a1.w + bqs[7];
        h[8] = a2.x + bqs[8]; h[9] = a2.y + bqs[9]; h[10]= a2.z + bqs[10];h[11]= a2.w + bqs[11];

        float s = 0.f;
#pragma unroll
        for (int j = 0; j < 12; j++) s += h[j];
#pragma unroll
        for (int off = 16; off; off >>= 1) s += __shfl_xor_sync(0xffffffffu, s, off);
        float mu = s * (1.f / C_);
        float v = 0.f;
#pragma unroll
        for (int j = 0; j < 12; j++) { float t = h[j] - mu; v += t * t; }
#pragma unroll
        for (int off = 16; off; off >>= 1) v += __shfl_xor_sync(0xffffffffu, v, off);
        float rstd = rsqrtf(v * (1.f / C_) + 1e-5f);

        float s0 = 0.f, s1 = 0.f, s2 = 0.f;
#pragma unroll
        for (int j = 0; j < 12; j++) {
            float g = (h[j] - mu) * rstd * lgs[j] + lbs[j];
            float y = 0.5f * g * (1.f + erff(g * 0.70710678118654752f));
            s0 = fmaf(y, w2s[j * 3 + 0], s0);
            s1 = fmaf(y, w2s[j * 3 + 1], s1);
            s2 = fmaf(y, w2s[j * 3 + 2], s2);
        }
#pragma unroll
        for (int off = 16; off; off >>= 1) {
            s0 += __shfl_xor_sync(0xffffffffu, s0, off);
            s1 += __shfl_xor_sync(0xffffffffu, s1, off);
            s2 += __shfl_xor_sync(0xffffffffu, s2, off);
        }
        if (lane == 0) {
            const int e = p * K_ + k;
            const float* pp = q_pos + (size_t)rownb * 3;
            g_shift[e * 3 + 0] = fmaf(tanhf(s0), sx, pp[0]);
            g_shift[e * 3 + 1] = fmaf(tanhf(s1), sy, pp[1]);
            g_shift[e * 3 + 2] = fmaf(tanhf(s2), sz, pp[2]);
        }
    }
}

// ---------------- three_nn: warp-per-point, 2 passes x 5 edges ----------------
__global__ __launch_bounds__(256) void three_nn_kernel(const float* __restrict__ q_pos) {
    __shared__ float4 sP[N_];
    const int pbase = blockIdx.x * 8;
    const int b = pbase >> 11;
    const float* P = q_pos + (size_t)b * N_ * 3;
    for (int i = threadIdx.x; i < N_; i += 256) {
        float x = P[i * 3 + 0], y = P[i * 3 + 1], z = P[i * 3 + 2];
        sP[i] = make_float4(x, y, z, x * x + y * y + z * z);
    }
    __syncthreads();
    const int w = threadIdx.x >> 5, lane = threadIdx.x & 31;
    const int p = pbase + w;
    const float FINF = __int_as_float(0x7f800000);

    for (int g = 0; g < 2; g++) {
        const int e0 = p * K_ + g * 5;
        float px[5], py[5], pz[5], qw[5];
#pragma unroll
        for (int j = 0; j < 5; j++) {
            px[j] = g_shift[(e0 + j) * 3 + 0];
            py[j] = g_shift[(e0 + j) * 3 + 1];
            pz[j] = g_shift[(e0 + j) * 3 + 2];
            qw[j] = px[j] * px[j] + py[j] * py[j] + pz[j] * pz[j];
        }
        float d0[5], d1[5], d2[5];
        int   i0[5], i1[5], i2[5];
#pragma unroll
        for (int j = 0; j < 5; j++) {
            d0[j] = d1[j] = d2[j] = FINF;
            i0[j] = i1[j] = i2[j] = 0x7fffffff;
        }

        for (int t = 0; t < N_ / 32; t++) {
            int cand = t * 32 + lane;
            float4 c = sP[cand];
#pragma unroll
            for (int j = 0; j < 5; j++) {
                float dot = px[j] * c.x + py[j] * c.y + pz[j] * c.z;
                float dp = fmaf(dot, -2.f, c.w);
                if (dp < d2[j]) {
                    if (dp < d1[j]) {
                        d2[j] = d1[j]; i2[j] = i1[j];
                        if (dp < d0[j]) {
                            d1[j] = d0[j]; i1[j] = i0[j];
                            d0[j] = dp;    i0[j] = cand;
                        } else {
                            d1[j] = dp;    i1[j] = cand;
                        }
                    } else {
                        d2[j] = dp; i2[j] = cand;
                    }
                }
            }
        }

#pragma unroll
        for (int j = 0; j < 5; j++) {
            float rd[3]; int ri[3];
            float a0 = d0[j], a1 = d1[j], a2 = d2[j];
            int   b0 = i0[j], b1 = i1[j], b2 = i2[j];
#pragma unroll
            for (int r = 0; r < 3; r++) {
                float bd = a0; int bi = b0;
#pragma unroll
                for (int off = 16; off; off >>= 1) {
                    float od = __shfl_xor_sync(0xffffffffu, bd, off);
                    int   oi = __shfl_xor_sync(0xffffffffu, bi, off);
                    if (dless(od, oi, bd, bi)) { bd = od; bi = oi; }
                }
                rd[r] = bd; ri[r] = bi;
                if (b0 == bi) { a0 = a1; b0 = b1; a1 = a2; b1 = b2;
                                a2 = FINF; b2 = 0x7fffffff; }
            }
            if (lane == 0) {
                const int e = e0 + j;
                float r0 = 1.f / (rd[0] + qw[j] + 1e-8f);
                float r1 = 1.f / (rd[1] + qw[j] + 1e-8f);
                float r2 = 1.f / (rd[2] + qw[j] + 1e-8f);
                float sm = r0 + r1 + r2;
                g_i3[e * 3 + 0] = ri[0]; g_w3[e * 3 + 0] = r0 / sm;
                g_i3[e * 3 + 1] = ri[1]; g_w3[e * 3 + 1] = r1 / sm;
                g_i3[e * 3 + 2] = ri[2]; g_w3[e * 3 + 2] = r2 / sm;
            }
        }
    }
}

// ---------------- final ----------------
__global__ __launch_bounds__(96) void final_kernel(float* __restrict__ out) {
    const int row = blockIdx.x;
    const int b = row >> 11;
    const int tid = threadIdx.x;
    __shared__ int   sI[K_ * 3];
    __shared__ float sW[K_ * 3];
    const int e0 = row * K_;
    if (tid < K_ * 3) { sI[tid] = g_i3[e0 * 3 + tid]; sW[tid] = g_w3[e0 * 3 + tid]; }
    __syncthreads();

    const size_t baseB = (size_t)b * N_ * LDQ;
    float4 qp = *(const float4*)(g_Q + (size_t)row * LDQ + 3 * C_ + tid * 4);
    const float NINF = __int_as_float(0xff800000);
    float4 mx = make_float4(NINF, NINF, NINF, NINF);

    for (int k = 0; k < K_; k++) {
        int   a0 = sI[3 * k + 0], a1 = sI[3 * k + 1], a2 = sI[3 * k + 2];
        float w0 = sW[3 * k + 0], w1 = sW[3 * k + 1], w2 = sW[3 * k + 2];
        float4 r0 = *(const float4*)(g_Q + baseB + (size_t)a0 * LDQ + 2 * C_ + tid * 4);
        float4 r1 = *(const float4*)(g_Q + baseB + (size_t)a1 * LDQ + 2 * C_ + tid * 4);
        float4 r2 = *(const float4*)(g_Q + baseB + (size_t)a2 * LDQ + 2 * C_ + tid * 4);
        float v0 = qp.x + w0 * r0.x + w1 * r1.x + w2 * r2.x;
        float v1 = qp.y + w0 * r0.y + w1 * r1.y + w2 * r2.y;
        float v2 = qp.z + w0 * r0.z + w1 * r1.z + w2 * r2.z;
        float v3 = qp.w + w0 * r0.w + w1 * r1.w + w2 * r2.w;
        v0 = v0 > 0.f ? v0 : 0.2f * v0;
        v1 = v1 > 0.f ? v1 : 0.2f * v1;
        v2 = v2 > 0.f ? v2 : 0.2f * v2;
        v3 = v3 > 0.f ? v3 : 0.2f * v3;
        mx.x = fmaxf(mx.x, v0); mx.y = fmaxf(mx.y, v1);
        mx.z = fmaxf(mx.z, v2); mx.w = fmaxf(mx.w, v3);
    }
    *(float4*)(out + (size_t)row * C_ + tid * 4) = mx;
}

// ---------------- launch ----------------
extern "C" void kernel_launch(void* const* d_in, const int* in_sizes, int n_in,
                              void* d_out, int out_size) {
    const float* q     = (const float*)d_in[0];
    const float* q_pos = (const float*)d_in[1];
    const float* Wv    = (const float*)d_in[2];
    const float* bv    = (const float*)d_in[3];
    const float* W1    = (const float*)d_in[4];
    const float* b1    = (const float*)d_in[5];
    const float* ln_g  = (const float*)d_in[6];
    const float* ln_b  = (const float*)d_in[7];
    const float* W2    = (const float*)d_in[8];
    const float* Wk    = (const float*)d_in[9];
    const float* bk    = (const float*)d_in[10];

    cudaFuncSetAttribute(gemm_mma, cudaFuncAttributeMaxDynamicSharedMemorySize, G_TOT);

    prep_wbig<<<(C_ * (LDQ - C_) + 255) / 256, 256>>>(W1, Wk);
    prep_bias<<<48 + (LDQ - C_ + 255) / 256, 256>>>(bv, W1, b1, bk);
    sgemm128<<<dim3(C_ / 128, C_ / 128), 256>>>(Wv, W1, F_DST_WBIG,
                                                C_, C_, C_, C_, C_, LDQ);
    conv_all<<<QELEMS / 256 + WELEMS / 256, 256>>>(q);
    knn_kernel<<<ROWS_ / 8, 256>>>(q_pos);
    gemm_mma<<<dim3(LDQ / 64, ROWS_ / 128), 256, G_TOT>>>();
    offset_kernel<<<ROWS_ / 8, 256>>>(q_pos, ln_g, ln_b, W2);
    three_nn_kernel<<<ROWS_ / 8, 256>>>(q_pos);
    final_kernel<<<ROWS_, 96>>>((float*)d_out);
}